// round 1
// baseline (speedup 1.0000x reference)
#include <cuda_runtime.h>
#include <math.h>

#define BB 32
#define TT 200
#define TM 199
#define NN (BB*TM)        // 6368
#define DD 100
#define KK 10
#define R2 (NN*16)        // 101888
#define R1 (NN*4)         // 25472
#define RH (NN*11)        // 70048

// ---------------- scratch (static device memory; no runtime allocation) ---------------
__device__ float g_buf[46486400];
__device__ int   g_topk[NN*KK];

static constexpr size_t OFF_X2  = 0;
static constexpr size_t OFF_E2  = 10188800;
static constexpr size_t OFF_X1  = 20377600;
static constexpr size_t OFF_E1  = 22924800;
static constexpr size_t OFF_E0A = 25472000;
static constexpr size_t OFF_E0B = 26108800;
static constexpr size_t OFF_X0  = 26745600;
static constexpr size_t OFF_AGG = 27382400;
static constexpr size_t OFF_XL  = 28019200;
static constexpr size_t OFF_G   = 29292800;
static constexpr size_t OFF_L   = 31840000;
static constexpr size_t OFF_XH  = 32476800;
static constexpr size_t OFF_KT  = 39481600;

// ---------------- gather / mean kernels (one warp per row) ---------------

__global__ void build_x2_k(const int* __restrict__ question, const int* __restrict__ q_nb,
                           const int* __restrict__ s_nb, const float* __restrict__ emb_q,
                           const float* __restrict__ emb_s, float* __restrict__ X2) {
    int row = blockIdx.x*4 + (threadIdx.x>>5);
    if (row >= R2) return;
    int lane = threadIdx.x & 31;
    int n = row >> 4, k = (row >> 2) & 3, s = row & 3;
    int b = n / TM, t = n - b*TM;
    int q  = question[b*TT + t];
    int sk = q_nb[q*4 + k];
    int q2 = s_nb[sk*4 + s];
    int m0 = q_nb[q2*4+0], m1 = q_nb[q2*4+1], m2 = q_nb[q2*4+2], m3 = q_nb[q2*4+3];
    const float* eq = emb_q + (size_t)q2*DD;
    const float* e0 = emb_s + (size_t)m0*DD;
    const float* e1 = emb_s + (size_t)m1*DD;
    const float* e2 = emb_s + (size_t)m2*DD;
    const float* e3 = emb_s + (size_t)m3*DD;
    float* xo = X2 + (size_t)row*DD;
    for (int d = lane; d < DD; d += 32)
        xo[d] = eq[d] + 0.25f*(e0[d]+e1[d]+e2[d]+e3[d]);
}

__global__ void build_x1_k(const int* __restrict__ question, const int* __restrict__ q_nb,
                           const int* __restrict__ s_nb, const float* __restrict__ emb_q,
                           const float* __restrict__ emb_s, float* __restrict__ X1) {
    int row = blockIdx.x*4 + (threadIdx.x>>5);
    if (row >= R1) return;
    int lane = threadIdx.x & 31;
    int n = row >> 2, k = row & 3;
    int b = n / TM, t = n - b*TM;
    int q  = question[b*TT + t];
    int sk = q_nb[q*4 + k];
    int s0 = s_nb[sk*4+0], s1 = s_nb[sk*4+1], s2 = s_nb[sk*4+2], s3 = s_nb[sk*4+3];
    const float* es = emb_s + (size_t)sk*DD;
    const float* e0 = emb_q + (size_t)s0*DD;
    const float* e1 = emb_q + (size_t)s1*DD;
    const float* e2 = emb_q + (size_t)s2*DD;
    const float* e3 = emb_q + (size_t)s3*DD;
    float* xo = X1 + (size_t)row*DD;
    for (int d = lane; d < DD; d += 32)
        xo[d] = es[d] + 0.25f*(e0[d]+e1[d]+e2[d]+e3[d]);
}

__global__ void build_x0_k(const int* __restrict__ question, const int* __restrict__ q_nb,
                           const float* __restrict__ emb_q, const float* __restrict__ emb_s,
                           float* __restrict__ X0) {
    int n = blockIdx.x*4 + (threadIdx.x>>5);
    if (n >= NN) return;
    int lane = threadIdx.x & 31;
    int b = n / TM, t = n - b*TM;
    int q = question[b*TT + t];
    int k0 = q_nb[q*4+0], k1 = q_nb[q*4+1], k2 = q_nb[q*4+2], k3 = q_nb[q*4+3];
    const float* eq = emb_q + (size_t)q*DD;
    const float* e0 = emb_s + (size_t)k0*DD;
    const float* e1 = emb_s + (size_t)k1*DD;
    const float* e2 = emb_s + (size_t)k2*DD;
    const float* e3 = emb_s + (size_t)k3*DD;
    float* xo = X0 + (size_t)n*DD;
    for (int d = lane; d < DD; d += 32)
        xo[d] = eq[d] + 0.25f*(e0[d]+e1[d]+e2[d]+e3[d]);
}

__global__ void mean4_add_k(const float* __restrict__ base, const float* __restrict__ kids,
                            float* __restrict__ X, int R) {
    int row = blockIdx.x*4 + (threadIdx.x>>5);
    if (row >= R) return;
    int lane = threadIdx.x & 31;
    const float* b0 = kids + (size_t)(row*4+0)*DD;
    const float* b1 = kids + (size_t)(row*4+1)*DD;
    const float* b2 = kids + (size_t)(row*4+2)*DD;
    const float* b3 = kids + (size_t)(row*4+3)*DD;
    const float* bb = base + (size_t)row*DD;
    float* xo = X + (size_t)row*DD;
    for (int d = lane; d < DD; d += 32)
        xo[d] = bb[d] + 0.25f*(b0[d]+b1[d]+b2[d]+b3[d]);
}

// ---------------- generic Y = tanh(X @ W^T + b), D=100 ---------------
// 256 threads, 32 rows/block. W in smem pitch 101 (conflict-free: 101 mod 32 = 5).
// 4x4 register micro-tile per thread: 16 FFMA per 8 LDS (4 of them broadcasts).

__global__ void affine_tanh_k(const float* __restrict__ X, const float* __restrict__ W,
                              const float* __restrict__ bias, float* __restrict__ Y, int R) {
    extern __shared__ float sm[];
    float* Ws = sm;              // 100*101
    float* Xs = sm + 100*101;    // 32*101
    float* bs = Xs + 32*101;     // 100
    int tid = threadIdx.x;
    for (int i = tid; i < 100*100; i += 256) {
        int o = i/100, d = i - o*100;
        Ws[o*101 + d] = W[i];
    }
    if (tid < 100) bs[tid] = bias[tid];
    int r0 = blockIdx.x*32;
    for (int i = tid; i < 32*100; i += 256) {
        int rr = i/100, d = i - rr*100;
        int r = r0 + rr;
        Xs[rr*101 + d] = (r < R) ? X[(size_t)r*100 + d] : 0.f;
    }
    __syncthreads();
    int cx = tid & 31, ry = tid >> 5;
    float acc[4][4];
    #pragma unroll
    for (int k = 0; k < 4; k++)
        #pragma unroll
        for (int c = 0; c < 4; c++) acc[k][c] = 0.f;
    int col3 = (cx < 4) ? (96 + cx) : 96;
    #pragma unroll 4
    for (int d = 0; d < 100; d++) {
        float xv[4];
        #pragma unroll
        for (int k = 0; k < 4; k++) xv[k] = Xs[(ry + 8*k)*101 + d];
        float w0 = Ws[cx*101+d], w1 = Ws[(cx+32)*101+d],
              w2 = Ws[(cx+64)*101+d], w3 = Ws[col3*101+d];
        #pragma unroll
        for (int k = 0; k < 4; k++) {
            acc[k][0] += xv[k]*w0; acc[k][1] += xv[k]*w1;
            acc[k][2] += xv[k]*w2; acc[k][3] += xv[k]*w3;
        }
    }
    #pragma unroll
    for (int k = 0; k < 4; k++) {
        int r = r0 + ry + 8*k;
        if (r >= R) continue;
        float* yo = Y + (size_t)r*100;
        yo[cx]      = tanhf(acc[k][0] + bs[cx]);
        yo[cx+32]   = tanhf(acc[k][1] + bs[cx+32]);
        yo[cx+64]   = tanhf(acc[k][2] + bs[cx+64]);
        if (cx < 4) yo[96+cx] = tanhf(acc[k][3] + bs[96+cx]);
    }
}

// ---------------- LSTM gates: G[:, ob:ob+100] = X(200) @ Wih[ob:ob+100]^T + b ---------------
// Only gate columns {0..99, 200..399} are ever used (forget gate is dead): grid.y = 3.

__global__ void gates_k(const float* __restrict__ X, const float* __restrict__ W,
                        const float* __restrict__ bias, float* __restrict__ G, int R) {
    extern __shared__ float sm[];
    float* Ws = sm;              // 100*201 (201 mod 32 = 9, conflict-free)
    float* Xs = sm + 100*201;    // 32*201
    float* bs = Xs + 32*201;     // 100
    int tid = threadIdx.x;
    int ob = (blockIdx.y == 0) ? 0 : (blockIdx.y + 1)*100;   // 0, 200, 300
    for (int i = tid; i < 100*200; i += 256) {
        int o = i/200, d = i - o*200;
        Ws[o*201 + d] = W[(size_t)(ob + o)*200 + d];
    }
    if (tid < 100) bs[tid] = bias[ob + tid];
    int r0 = blockIdx.x*32;
    for (int i = tid; i < 32*200; i += 256) {
        int rr = i/200, d = i - rr*200;
        int r = r0 + rr;
        Xs[rr*201 + d] = (r < R) ? X[(size_t)r*200 + d] : 0.f;
    }
    __syncthreads();
    int cx = tid & 31, ry = tid >> 5;
    float acc[4][4];
    #pragma unroll
    for (int k = 0; k < 4; k++)
        #pragma unroll
        for (int c = 0; c < 4; c++) acc[k][c] = 0.f;
    int col3 = (cx < 4) ? (96 + cx) : 96;
    #pragma unroll 2
    for (int d = 0; d < 200; d++) {
        float xv[4];
        #pragma unroll
        for (int k = 0; k < 4; k++) xv[k] = Xs[(ry + 8*k)*201 + d];
        float w0 = Ws[cx*201+d], w1 = Ws[(cx+32)*201+d],
              w2 = Ws[(cx+64)*201+d], w3 = Ws[col3*201+d];
        #pragma unroll
        for (int k = 0; k < 4; k++) {
            acc[k][0] += xv[k]*w0; acc[k][1] += xv[k]*w1;
            acc[k][2] += xv[k]*w2; acc[k][3] += xv[k]*w3;
        }
    }
    #pragma unroll
    for (int k = 0; k < 4; k++) {
        int r = r0 + ry + 8*k;
        if (r >= R) continue;
        float* go = G + (size_t)r*400 + ob;
        go[cx]      = acc[k][0] + bs[cx];
        go[cx+32]   = acc[k][1] + bs[cx+32];
        go[cx+64]   = acc[k][2] + bs[cx+64];
        if (cx < 4) go[96+cx] = acc[k][3] + bs[96+cx];
    }
}

// ---------------- misc pointwise ---------------

__global__ void build_xl_k(const int* __restrict__ question, const int* __restrict__ response,
                           const int* __restrict__ mask, const float* __restrict__ emb_q,
                           const float* __restrict__ emb_r, const float* __restrict__ AGG,
                           float* __restrict__ XL) {
    int n = blockIdx.x*4 + (threadIdx.x>>5);
    if (n >= NN) return;
    int lane = threadIdx.x & 31;
    int b = n / TM, t = n - b*TM;
    int q = question[b*TT + t];
    int m = mask[b*TT + t];
    int r = response[b*TT + t];
    const float* src = (m == 1) ? (AGG + (size_t)n*DD) : (emb_q + (size_t)q*DD);
    const float* er  = emb_r + (size_t)r*DD;
    float* xo = XL + (size_t)n*2*DD;
    for (int d = lane; d < DD; d += 32) { xo[d] = src[d]; xo[DD+d] = er[d]; }
}

__global__ void lstm_pw_k(const float* __restrict__ G, float* __restrict__ L) {
    int i = blockIdx.x*blockDim.x + threadIdx.x;
    if (i >= NN*DD) return;
    int n = i/DD, d = i - n*DD;
    const float* g = G + (size_t)n*400;
    float gi = g[d], gg = g[200+d], go = g[300+d];
    float si = 1.f/(1.f + expf(-gi));
    float so = 1.f/(1.f + expf(-go));
    L[i] = so * tanhf(si * tanhf(gg));
}

// ---------------- attention-history scores + per-t top-10 ---------------
// grid (B, 25); warp w handles t = blockIdx.y*8 + w. plain rows staged in smem (pitch 101).

__global__ void scores_topk_k(const int* __restrict__ question,
                              const float* __restrict__ emb_q,
                              int* __restrict__ topk) {
    extern __shared__ float sm[];
    float* P    = sm;              // [199][101]
    float* qrow = P + 199*101;     // [8][104]
    float* srow = qrow + 8*104;    // [8][200]
    int b = blockIdx.x;
    int tid = threadIdx.x, w = tid >> 5, lane = tid & 31;
    int tmax = min(TM - 1, (int)blockIdx.y*8 + 7);
    int rmax = tmax;                // need plain rows s < t <= tmax
    for (int i = tid; i < rmax*DD; i += 256) {
        int s = i / DD, d = i - s*DD;
        P[s*101 + d] = emb_q[(size_t)question[b*TT + s]*DD + d];
    }
    __syncthreads();
    int t = blockIdx.y*8 + w;
    if (t >= TM) return;
    int qv = question[b*TT + t + 1];
    for (int d = lane; d < DD; d += 32) qrow[w*104 + d] = emb_q[(size_t)qv*DD + d];
    __syncwarp();
    for (int s = lane; s < t; s += 32) {
        float acc = 0.f;
        const float* pr = P + s*101;
        const float* qr = qrow + w*104;
        #pragma unroll 4
        for (int d = 0; d < DD; d++) acc += qr[d]*pr[d];
        srow[w*200 + s] = acc;
    }
    __syncwarp();
    int n = b*TM + t;
    int cnt = min(t, KK);
    for (int sel = 0; sel < KK; sel++) {
        if (sel < cnt) {
            float bv = -3.4e38f; unsigned bi = 0xffffffffu;
            for (int s = lane; s < t; s += 32) {
                float v = srow[w*200 + s];
                if (v > bv) { bv = v; bi = (unsigned)s; }
            }
            #pragma unroll
            for (int off = 16; off; off >>= 1) {
                float    ov = __shfl_down_sync(0xffffffffu, bv, off);
                unsigned oi = __shfl_down_sync(0xffffffffu, bi, off);
                if (ov > bv || (ov == bv && oi < bi)) { bv = ov; bi = oi; }
            }
            bi = __shfl_sync(0xffffffffu, bi, 0);
            if (lane == 0) { topk[n*KK + sel] = (int)bi; srow[w*200 + bi] = -3.4e38f; }
            __syncwarp();
        } else if (lane == 0) {
            topk[n*KK + sel] = -1;
        }
    }
}

__global__ void build_xh_k(const float* __restrict__ L, const int* __restrict__ topk,
                           float* __restrict__ XH) {
    int n = blockIdx.x;
    int b = n / TM, t = n - b*TM;
    int cnt = min(t, KK);
    for (int e = threadIdx.x; e < 11*DD; e += blockDim.x) {
        int s = e / DD, d = e - s*DD;
        float v = 0.f;
        if (s == 0) v = L[(size_t)n*DD + d];
        else if (s - 1 < cnt) {
            int idx = topk[n*KK + (s-1)];
            if (idx > 0) v = L[((size_t)b*TM + idx)*DD + d];   // idx==0 -> state_history row 0 is zeroed
        }
        XH[((size_t)n*11 + s)*DD + d] = v;
    }
}

// ---------------- final attention (qt/b_att cancel in softmax over s) ---------------

__global__ void final_k(const int* __restrict__ question, const int* __restrict__ skidx,
                        const int* __restrict__ skmask, const float* __restrict__ emb_q,
                        const float* __restrict__ emb_s, const float* __restrict__ XH,
                        const float* __restrict__ KT, const float* __restrict__ w_att,
                        float* __restrict__ out) {
    int n = blockIdx.x*4 + (threadIdx.x>>5);
    if (n >= NN) return;
    int lane = threadIdx.x & 31;
    int b = n / TM, t = n - b*TM;
    int qv = question[b*TT + t + 1];
    float qs[4], wv[4];
    #pragma unroll
    for (int k = 0; k < 4; k++) {
        int d = lane + 32*k;
        float v = 0.f;
        if (d < DD) {
            v = emb_q[(size_t)qv*DD + d];
            #pragma unroll
            for (int i = 0; i < 4; i++)
                if (skmask[qv*4 + i] != 0) v += emb_s[(size_t)skidx[qv*4 + i]*DD + d];
        }
        qs[k] = v;
        wv[k] = (d < DD) ? w_att[DD + d] : 0.f;
    }
    int cnt = min(t, KK);
    float kt[11], gv[11];
    #pragma unroll
    for (int s = 0; s < 11; s++) {
        float a = 0.f, g = 0.f;
        if (s <= cnt) {
            const float* hrow = XH + ((size_t)n*11 + s)*DD;
            const float* krow = KT + ((size_t)n*11 + s)*DD;
            #pragma unroll
            for (int k = 0; k < 4; k++) {
                int d = lane + 32*k;
                if (d < DD) { a += krow[d]*wv[k]; g += qs[k]*hrow[d]; }
            }
            #pragma unroll
            for (int off = 16; off; off >>= 1) {
                a += __shfl_down_sync(0xffffffffu, a, off);
                g += __shfl_down_sync(0xffffffffu, g, off);
            }
        }
        kt[s] = a; gv[s] = g;
    }
    if (lane == 0) {
        float m = -3.4e38f;
        #pragma unroll
        for (int s = 0; s < 11; s++) if (s <= cnt && kt[s] > m) m = kt[s];
        float Z = 0.f, P = 0.f;
        #pragma unroll
        for (int s = 0; s < 11; s++) if (s <= cnt) { float e = expf(kt[s]-m); Z += e; P += e*gv[s]; }
        float p = P / Z;
        out[b*TT + 1 + t] = 1.f/(1.f + expf(-p));
    }
}

__global__ void tail_k(const float* __restrict__ L, float* __restrict__ out) {
    int i = blockIdx.x*blockDim.x + threadIdx.x;
    if (i < BB) out[i*TT] = 0.5f;
    if (i < BB*DD) {
        int b = i / DD;
        out[BB*TT + i] = L[((size_t)b*TM + (TM-1))*DD + (i - b*DD)];
    }
}

// ---------------- launch ---------------

extern "C" void kernel_launch(void* const* d_in, const int* in_sizes, int n_in,
                              void* d_out, int out_size) {
    const int*   question = (const int*)d_in[0];
    const int*   response = (const int*)d_in[1];
    const int*   maskp    = (const int*)d_in[2];
    const int*   q_nb     = (const int*)d_in[3];
    const int*   s_nb     = (const int*)d_in[4];
    const int*   skidx    = (const int*)d_in[5];
    const int*   skmask   = (const int*)d_in[6];
    const float* emb_q    = (const float*)d_in[7];
    const float* emb_s    = (const float*)d_in[8];
    const float* emb_r    = (const float*)d_in[9];
    const float* Wih      = (const float*)d_in[10];
    const float* lb       = (const float*)d_in[11];
    const float* aggW     = (const float*)d_in[12];
    const float* aggb     = (const float*)d_in[13];
    const float* aggLW    = (const float*)d_in[14];
    const float* aggLb    = (const float*)d_in[15];
    const float* Wq       = (const float*)d_in[16];
    const float* bq       = (const float*)d_in[17];
    const float* w_att    = (const float*)d_in[20];
    float* out = (float*)d_out;

    float* buf  = nullptr;
    int*   topk = nullptr;
    cudaGetSymbolAddress((void**)&buf,  g_buf);
    cudaGetSymbolAddress((void**)&topk, g_topk);

    float* pX2  = buf + OFF_X2;
    float* pE2  = buf + OFF_E2;
    float* pX1  = buf + OFF_X1;
    float* pE1  = buf + OFF_E1;
    float* pE0a = buf + OFF_E0A;
    float* pE0b = buf + OFF_E0B;
    float* pX0  = buf + OFF_X0;
    float* pAGG = buf + OFF_AGG;
    float* pXL  = buf + OFF_XL;
    float* pG   = buf + OFF_G;
    float* pL   = buf + OFF_L;
    float* pXH  = buf + OFF_XH;
    float* pKT  = buf + OFF_KT;

    const int AFF_SMEM = (100*101 + 32*101 + 100)*4;
    const int GAT_SMEM = (100*201 + 32*201 + 100)*4;
    const int SCO_SMEM = (199*101 + 8*104 + 8*200)*4;
    cudaFuncSetAttribute(affine_tanh_k, cudaFuncAttributeMaxDynamicSharedMemorySize, AFF_SMEM);
    cudaFuncSetAttribute(gates_k,       cudaFuncAttributeMaxDynamicSharedMemorySize, GAT_SMEM);
    cudaFuncSetAttribute(scores_topk_k, cudaFuncAttributeMaxDynamicSharedMemorySize, SCO_SMEM);

    // ---- GNN aggregation (3 hops) ----
    build_x2_k<<<R2/4, 128>>>(question, q_nb, s_nb, emb_q, emb_s, pX2);
    affine_tanh_k<<<(R2+31)/32, 256, AFF_SMEM>>>(pX2, aggW + 2*DD*DD, aggb + 2*DD, pE2, R2);
    build_x1_k<<<R1/4, 128>>>(question, q_nb, s_nb, emb_q, emb_s, pX1);
    affine_tanh_k<<<(R1+31)/32, 256, AFF_SMEM>>>(pX1, aggW + DD*DD, aggb + DD, pE1, R1);
    build_x0_k<<<NN/4, 128>>>(question, q_nb, emb_q, emb_s, pX0);
    affine_tanh_k<<<(NN+31)/32, 256, AFF_SMEM>>>(pX0, aggW, aggb, pE0a, NN);          // e0 pass0
    mean4_add_k<<<NN/4, 128>>>(pE0a, pE1, pX0, NN);
    affine_tanh_k<<<(NN+31)/32, 256, AFF_SMEM>>>(pX0, aggW, aggb, pE0b, NN);          // e0 pass1
    mean4_add_k<<<R1/4, 128>>>(pE1, pE2, pX1, R1);
    affine_tanh_k<<<(R1+31)/32, 256, AFF_SMEM>>>(pX1, aggW + DD*DD, aggb + DD, pE1, R1); // e1 pass1
    mean4_add_k<<<NN/4, 128>>>(pE0b, pE1, pX0, NN);
    affine_tanh_k<<<(NN+31)/32, 256, AFF_SMEM>>>(pX0, aggW, aggb, pE0a, NN);          // e0 pass2
    affine_tanh_k<<<(NN+31)/32, 256, AFF_SMEM>>>(pE0a, aggLW, aggLb, pAGG, NN);       // final agg

    // ---- LSTM (gate-parallel; forget gate dead) ----
    build_xl_k<<<NN/4, 128>>>(question, response, maskp, emb_q, emb_r, pAGG, pXL);
    gates_k<<<dim3((NN+31)/32, 3), 256, GAT_SMEM>>>(pXL, Wih, lb, pG, NN);
    lstm_pw_k<<<(NN*DD + 255)/256, 256>>>(pG, pL);

    // ---- scores + top-10 ----
    scores_topk_k<<<dim3(BB, 25), 256, SCO_SMEM>>>(question, emb_q, topk);

    // ---- attention ----
    build_xh_k<<<NN, 128>>>(pL, topk, pXH);
    affine_tanh_k<<<(RH+31)/32, 256, AFF_SMEM>>>(pXH, Wq, bq, pKT, RH);
    final_k<<<NN/4, 128>>>(question, skidx, skmask, emb_q, emb_s, pXH, pKT, w_att, out);
    tail_k<<<(BB*DD + 255)/256, 256>>>(pL, out);
}

// round 3
// speedup vs baseline: 1.3773x; 1.3773x over previous
#include <cuda_runtime.h>
#include <math.h>

#define BB 32
#define TT 200
#define TM 199
#define NN (BB*TM)        // 6368
#define DD 100
#define KK 10
#define R2 (NN*16)        // 101888
#define R1 (NN*4)         // 25472
#define RH (NN*11)        // 70048

typedef unsigned long long ull;

// ---------------- scratch (static device memory) ----------------
__device__ float g_buf[34387200];
__device__ float g_kt[RH];
__device__ int   g_topk[NN*KK];

static constexpr size_t OFF_X2  = 0;
static constexpr size_t OFF_E2  = 10188800;
static constexpr size_t OFF_X1  = 20377600;
static constexpr size_t OFF_E1  = 22924800;
static constexpr size_t OFF_X0  = 25472000;
static constexpr size_t OFF_E0A = 26108800;
static constexpr size_t OFF_E0B = 26745600;
static constexpr size_t OFF_E0C = 27382400;
static constexpr size_t OFF_E1B = 28019200;
static constexpr size_t OFF_AGG = 30566400;
static constexpr size_t OFF_G   = 31203200;
static constexpr size_t OFF_L   = 33750400;

// ---------------- helpers ----------------
__device__ __forceinline__ void fma2(ull& a, ull x, ull w){
    asm("fma.rn.f32x2 %0, %1, %2, %0;" : "+l"(a) : "l"(x), "l"(w));
}
__device__ __forceinline__ float unpack_sum(ull a){
    float lo = __int_as_float((int)(unsigned int)a);
    float hi = __int_as_float((int)(unsigned int)(a >> 32));
    return lo + hi;
}
__device__ __forceinline__ float ftanh(float x){
    float e = __expf(2.f*x);
    return 1.f - __fdividef(2.f, e + 1.f);
}
__device__ __forceinline__ float fsig(float x){
    return __fdividef(1.f, 1.f + __expf(-x));
}

// ---------------- gather kernels (one warp per row) ----------------

__global__ void build_x2_k(const int* __restrict__ question, const int* __restrict__ q_nb,
                           const int* __restrict__ s_nb, const float* __restrict__ emb_q,
                           const float* __restrict__ emb_s, float* __restrict__ X2) {
    int row = blockIdx.x*4 + (threadIdx.x>>5);
    if (row >= R2) return;
    int lane = threadIdx.x & 31;
    int n = row >> 4, k = (row >> 2) & 3, s = row & 3;
    int b = n / TM, t = n - b*TM;
    int q  = question[b*TT + t];
    int sk = q_nb[q*4 + k];
    int q2 = s_nb[sk*4 + s];
    int m0 = q_nb[q2*4+0], m1 = q_nb[q2*4+1], m2 = q_nb[q2*4+2], m3 = q_nb[q2*4+3];
    const float* eq = emb_q + (size_t)q2*DD;
    const float* e0 = emb_s + (size_t)m0*DD;
    const float* e1 = emb_s + (size_t)m1*DD;
    const float* e2 = emb_s + (size_t)m2*DD;
    const float* e3 = emb_s + (size_t)m3*DD;
    float* xo = X2 + (size_t)row*DD;
    for (int d = lane; d < DD; d += 32)
        xo[d] = eq[d] + 0.25f*(e0[d]+e1[d]+e2[d]+e3[d]);
}

__global__ void build_x1_k(const int* __restrict__ question, const int* __restrict__ q_nb,
                           const int* __restrict__ s_nb, const float* __restrict__ emb_q,
                           const float* __restrict__ emb_s, float* __restrict__ X1) {
    int row = blockIdx.x*4 + (threadIdx.x>>5);
    if (row >= R1) return;
    int lane = threadIdx.x & 31;
    int n = row >> 2, k = row & 3;
    int b = n / TM, t = n - b*TM;
    int q  = question[b*TT + t];
    int sk = q_nb[q*4 + k];
    int s0 = s_nb[sk*4+0], s1 = s_nb[sk*4+1], s2 = s_nb[sk*4+2], s3 = s_nb[sk*4+3];
    const float* es = emb_s + (size_t)sk*DD;
    const float* e0 = emb_q + (size_t)s0*DD;
    const float* e1 = emb_q + (size_t)s1*DD;
    const float* e2 = emb_q + (size_t)s2*DD;
    const float* e3 = emb_q + (size_t)s3*DD;
    float* xo = X1 + (size_t)row*DD;
    for (int d = lane; d < DD; d += 32)
        xo[d] = es[d] + 0.25f*(e0[d]+e1[d]+e2[d]+e3[d]);
}

__global__ void build_x0_k(const int* __restrict__ question, const int* __restrict__ q_nb,
                           const float* __restrict__ emb_q, const float* __restrict__ emb_s,
                           float* __restrict__ X0) {
    int n = blockIdx.x*4 + (threadIdx.x>>5);
    if (n >= NN) return;
    int lane = threadIdx.x & 31;
    int b = n / TM, t = n - b*TM;
    int q = question[b*TT + t];
    int k0 = q_nb[q*4+0], k1 = q_nb[q*4+1], k2 = q_nb[q*4+2], k3 = q_nb[q*4+3];
    const float* eq = emb_q + (size_t)q*DD;
    const float* e0 = emb_s + (size_t)k0*DD;
    const float* e1 = emb_s + (size_t)k1*DD;
    const float* e2 = emb_s + (size_t)k2*DD;
    const float* e3 = emb_s + (size_t)k3*DD;
    float* xo = X0 + (size_t)n*DD;
    for (int d = lane; d < DD; d += 32)
        xo[d] = eq[d] + 0.25f*(e0[d]+e1[d]+e2[d]+e3[d]);
}

// ---------------- fused affine: Y = tanh(X @ W^T + b), 48 rows/block ----------------
// MODE 0: X from gmem. MODE 1: X = base + 0.25*sum(kids[4r..4r+3]).
// MODE 2: X gathered from L via topk (hist rows); DOT=true emits dot(tanh,w2) scalar.
// W smem pitch 102 floats (51 8B-words: conflict-free LDS.64), X pitch 104 (16B aligned).
// f32x2 packed FMA: acc holds (even-d, odd-d) partial sums per (row,col).

struct AP {
    const float* X; const float* base; const float* kids;
    const float* L; const int* topk;
    const float* W; const float* bias; const float* w2;
    float* Y;
};

template<int MODE, bool DOT>
__global__ __launch_bounds__(256) void affine48_k(AP p, int R){
    extern __shared__ float sm[];
    float* Ws  = sm;               // 100 x 102
    float* Xs  = sm + 10200;       // 48 x 104
    float* bs  = Xs + 48*104;      // 100
    float* w2s = bs + 100;         // 100
    int tid = threadIdx.x;

    for (int j = tid; j < 2500; j += 256){
        float4 v = ((const float4*)p.W)[j];
        int b4 = 4*j; int o = b4/100; int d = b4 - o*100;
        float2* ws = (float2*)&Ws[o*102 + d];
        ws[0] = make_float2(v.x, v.y);
        ws[1] = make_float2(v.z, v.w);
    }
    if (tid < 100) bs[tid] = p.bias[tid];
    if (DOT) { if (tid >= 128 && tid < 228) w2s[tid-128] = p.w2[tid-128]; }

    int wy = tid >> 5, lane = tid & 31;
    int r0 = blockIdx.x * 48;

    for (int rr = wy; rr < 48; rr += 8){
        if (lane < 25){
            int r = r0 + rr;
            float4 val = make_float4(0.f,0.f,0.f,0.f);
            if (r < R){
                if (MODE == 0){
                    val = ((const float4*)(p.X + (size_t)r*100))[lane];
                } else if (MODE == 1){
                    const float4* bp = (const float4*)(p.base + (size_t)r*100);
                    const float4* kp = (const float4*)(p.kids + (size_t)r*400);
                    float4 a = kp[lane], b = kp[25+lane], c = kp[50+lane], d4 = kp[75+lane];
                    float4 bb = bp[lane];
                    val.x = bb.x + 0.25f*(a.x+b.x+c.x+d4.x);
                    val.y = bb.y + 0.25f*(a.y+b.y+c.y+d4.y);
                    val.z = bb.z + 0.25f*(a.z+b.z+c.z+d4.z);
                    val.w = bb.w + 0.25f*(a.w+b.w+c.w+d4.w);
                } else {
                    int n = r / 11, s = r - n*11;
                    int b = n / TM, t = n - b*TM;
                    int cnt = min(t, KK);
                    const float* src = nullptr;
                    if (s == 0) src = p.L + (size_t)n*100;
                    else if (s-1 < cnt){
                        int idx = p.topk[n*KK + s - 1];
                        if (idx > 0) src = p.L + ((size_t)b*TM + idx)*100;
                    }
                    if (src) val = ((const float4*)src)[lane];
                }
            }
            *(float4*)&Xs[rr*104 + 4*lane] = val;
        }
    }
    __syncthreads();

    int c3 = (lane < 4) ? 96 + lane : 96;
    int col[4] = {lane, lane+32, lane+64, c3};
    ull acc[6][4];
    #pragma unroll
    for (int k = 0; k < 6; k++)
        #pragma unroll
        for (int c = 0; c < 4; c++) acc[k][c] = 0ull;

    const ull* WsU = (const ull*)Ws;
    const ull* XsU = (const ull*)Xs;
    int xbase = wy*6*52;
    #pragma unroll 1
    for (int d = 0; d < 100; d += 4){
        int dw = d >> 1;
        ull w01[4], w23[4];
        #pragma unroll
        for (int c = 0; c < 4; c++){
            int wb = col[c]*51 + dw;
            w01[c] = WsU[wb]; w23[c] = WsU[wb+1];
        }
        #pragma unroll
        for (int k = 0; k < 6; k++){
            int xb = xbase + k*52 + dw;
            ull x01 = XsU[xb], x23 = XsU[xb+1];
            #pragma unroll
            for (int c = 0; c < 4; c++){
                fma2(acc[k][c], x01, w01[c]);
                fma2(acc[k][c], x23, w23[c]);
            }
        }
    }

    #pragma unroll
    for (int k = 0; k < 6; k++){
        int r = r0 + wy*6 + k;
        if (r >= R) continue;
        float o0 = ftanh(unpack_sum(acc[k][0]) + bs[col[0]]);
        float o1 = ftanh(unpack_sum(acc[k][1]) + bs[col[1]]);
        float o2 = ftanh(unpack_sum(acc[k][2]) + bs[col[2]]);
        float o3 = ftanh(unpack_sum(acc[k][3]) + bs[col[3]]);
        if (!DOT){
            float* yo = p.Y + (size_t)r*100;
            yo[col[0]] = o0; yo[col[1]] = o1; yo[col[2]] = o2;
            if (lane < 4) yo[col[3]] = o3;
        } else {
            float v = o0*w2s[col[0]] + o1*w2s[col[1]] + o2*w2s[col[2]];
            if (lane < 4) v += o3*w2s[col[3]];
            #pragma unroll
            for (int off = 16; off; off >>= 1) v += __shfl_down_sync(0xffffffffu, v, off);
            if (lane == 0) p.Y[r] = v;
        }
    }
}

// ---------------- fused LSTM gates (input build + 200-d GEMM), 32 rows/block ----------------
// grid.y in {0,1,2} -> gate offsets {0,200,300} (forget gate is dead).

__global__ __launch_bounds__(256) void gates32_k(
    const int* __restrict__ question, const int* __restrict__ response,
    const int* __restrict__ maskp, const float* __restrict__ emb_q,
    const float* __restrict__ emb_r, const float* __restrict__ AGG,
    const float* __restrict__ Wih, const float* __restrict__ lb,
    float* __restrict__ G){
    extern __shared__ float sm[];
    float* Ws = sm;             // 100 x 202
    float* Xs = sm + 20200;     // 32 x 204
    float* bs = Xs + 32*204;    // 100
    int tid = threadIdx.x;
    int ob = (blockIdx.y == 0) ? 0 : ((int)blockIdx.y + 1)*100;   // 0, 200, 300
    const float* W = Wih + (size_t)ob*200;

    for (int j = tid; j < 5000; j += 256){
        float4 v = ((const float4*)W)[j];
        int b4 = 4*j; int o = b4/200; int d = b4 - o*200;
        float2* ws = (float2*)&Ws[o*202 + d];
        ws[0] = make_float2(v.x, v.y);
        ws[1] = make_float2(v.z, v.w);
    }
    if (tid < 100) bs[tid] = lb[ob + tid];

    int wy = tid >> 5, lane = tid & 31;
    int r0 = blockIdx.x * 32;
    for (int rr = wy; rr < 32; rr += 8){
        if (lane < 25){
            int r = r0 + rr;
            float4 v1 = make_float4(0.f,0.f,0.f,0.f), v2 = v1;
            if (r < NN){
                int b = r / TM, t = r - b*TM;
                int q   = question[b*TT + t];
                int m   = maskp[b*TT + t];
                int rsp = response[b*TT + t];
                const float4* s1 = (const float4*)((m == 1) ? (AGG + (size_t)r*100)
                                                            : (emb_q + (size_t)q*100));
                const float4* s2 = (const float4*)(emb_r + (size_t)rsp*100);
                v1 = s1[lane]; v2 = s2[lane];
            }
            *(float4*)&Xs[rr*204 + 4*lane]       = v1;
            *(float4*)&Xs[rr*204 + 100 + 4*lane] = v2;
        }
    }
    __syncthreads();

    int c3 = (lane < 4) ? 96 + lane : 96;
    int col[4] = {lane, lane+32, lane+64, c3};
    ull acc[4][4];
    #pragma unroll
    for (int k = 0; k < 4; k++)
        #pragma unroll
        for (int c = 0; c < 4; c++) acc[k][c] = 0ull;

    const ull* WsU = (const ull*)Ws;
    const ull* XsU = (const ull*)Xs;
    int xbase = wy*4*102;
    #pragma unroll 1
    for (int d = 0; d < 200; d += 4){
        int dw = d >> 1;
        ull w01[4], w23[4];
        #pragma unroll
        for (int c = 0; c < 4; c++){
            int wb = col[c]*101 + dw;
            w01[c] = WsU[wb]; w23[c] = WsU[wb+1];
        }
        #pragma unroll
        for (int k = 0; k < 4; k++){
            int xb = xbase + k*102 + dw;
            ull x01 = XsU[xb], x23 = XsU[xb+1];
            #pragma unroll
            for (int c = 0; c < 4; c++){
                fma2(acc[k][c], x01, w01[c]);
                fma2(acc[k][c], x23, w23[c]);
            }
        }
    }

    #pragma unroll
    for (int k = 0; k < 4; k++){
        int r = r0 + wy*4 + k;
        if (r >= NN) continue;
        float* go = G + (size_t)r*400 + ob;
        go[col[0]] = unpack_sum(acc[k][0]) + bs[col[0]];
        go[col[1]] = unpack_sum(acc[k][1]) + bs[col[1]];
        go[col[2]] = unpack_sum(acc[k][2]) + bs[col[2]];
        if (lane < 4) go[col[3]] = unpack_sum(acc[k][3]) + bs[col[3]];
    }
}

// ---------------- LSTM pointwise ----------------
__global__ void lstm_pw_k(const float* __restrict__ G, float* __restrict__ L) {
    int i = blockIdx.x*blockDim.x + threadIdx.x;
    if (i >= NN*DD) return;
    int n = i/DD, d = i - n*DD;
    const float* g = G + (size_t)n*400;
    float gi = g[d], gg = g[200+d], go = g[300+d];
    L[i] = fsig(go) * ftanh(fsig(gi) * ftanh(gg));
}

// ---------------- scores + per-t top-10 ----------------
__global__ void scores_topk_k(const int* __restrict__ question,
                              const float* __restrict__ emb_q,
                              int* __restrict__ topk) {
    extern __shared__ float sm[];
    float* P    = sm;              // [199][101]
    float* qrow = P + 199*101;     // [8][104]
    float* srow = qrow + 8*104;    // [8][200]
    int*   qidx = (int*)(srow + 8*200);  // [200]
    int b = blockIdx.x;
    int tid = threadIdx.x, w = tid >> 5, lane = tid & 31;
    if (tid < TT) qidx[tid] = question[b*TT + tid];
    __syncthreads();
    int tmax = min(TM - 1, (int)blockIdx.y*8 + 7);
    int rmax = tmax;
    for (int i = tid; i < rmax*DD; i += 256) {
        int s = i / DD, d = i - s*DD;
        P[s*101 + d] = emb_q[(size_t)qidx[s]*DD + d];
    }
    __syncthreads();
    int t = blockIdx.y*8 + w;
    if (t >= TM) return;
    int qv = qidx[t + 1];
    for (int d = lane; d < DD; d += 32) qrow[w*104 + d] = emb_q[(size_t)qv*DD + d];
    __syncwarp();
    for (int s = lane; s < t; s += 32) {
        float acc = 0.f;
        const float* pr = P + s*101;
        const float* qr = qrow + w*104;
        #pragma unroll 4
        for (int d = 0; d < DD; d++) acc += qr[d]*pr[d];
        srow[w*200 + s] = acc;
    }
    __syncwarp();
    int n = b*TM + t;
    int cnt = min(t, KK);
    for (int sel = 0; sel < KK; sel++) {
        if (sel < cnt) {
            float bv = -3.4e38f; unsigned bi = 0xffffffffu;
            for (int s = lane; s < t; s += 32) {
                float v = srow[w*200 + s];
                if (v > bv) { bv = v; bi = (unsigned)s; }
            }
            #pragma unroll
            for (int off = 16; off; off >>= 1) {
                float    ov = __shfl_down_sync(0xffffffffu, bv, off);
                unsigned oi = __shfl_down_sync(0xffffffffu, bi, off);
                if (ov > bv || (ov == bv && oi < bi)) { bv = ov; bi = oi; }
            }
            bi = __shfl_sync(0xffffffffu, bi, 0);
            if (lane == 0) { topk[n*KK + sel] = (int)bi; srow[w*200 + bi] = -3.4e38f; }
            __syncwarp();
        } else if (lane == 0) {
            topk[n*KK + sel] = -1;
        }
    }
}

// ---------------- final attention (kt precomputed; hist read straight from L) ----------------
__global__ void final_k(const int* __restrict__ question, const int* __restrict__ skidx,
                        const int* __restrict__ skmask, const float* __restrict__ emb_q,
                        const float* __restrict__ emb_s, const float* __restrict__ L,
                        const int* __restrict__ topk, const float* __restrict__ ktbuf,
                        float* __restrict__ out) {
    int n = blockIdx.x*4 + (threadIdx.x>>5);
    if (n >= NN) return;
    int lane = threadIdx.x & 31;
    int b = n / TM, t = n - b*TM;
    int qv = question[b*TT + t + 1];
    float qs[4];
    #pragma unroll
    for (int k = 0; k < 4; k++) {
        int d = lane + 32*k;
        float v = 0.f;
        if (d < DD) {
            v = emb_q[(size_t)qv*DD + d];
            #pragma unroll
            for (int i = 0; i < 4; i++)
                if (skmask[qv*4 + i] != 0) v += emb_s[(size_t)skidx[qv*4 + i]*DD + d];
        }
        qs[k] = v;
    }
    int cnt = min(t, KK);
    float gv[11];
    #pragma unroll
    for (int s = 0; s < 11; s++) {
        const float* src = nullptr;
        if (s == 0) src = L + (size_t)n*DD;
        else if (s-1 < cnt) {
            int idx = topk[n*KK + s - 1];
            if (idx > 0) src = L + ((size_t)b*TM + idx)*DD;
        }
        float g = 0.f;
        if (src) {
            #pragma unroll
            for (int k = 0; k < 4; k++) {
                int d = lane + 32*k;
                if (d < DD) g += qs[k]*src[d];
            }
            #pragma unroll
            for (int off = 16; off; off >>= 1)
                g += __shfl_down_sync(0xffffffffu, g, off);
        }
        gv[s] = g;
    }
    if (lane == 0) {
        float kt[11];
        #pragma unroll
        for (int s = 0; s < 11; s++) kt[s] = (s <= cnt) ? ktbuf[n*11 + s] : -3.4e38f;
        float m = -3.4e38f;
        #pragma unroll
        for (int s = 0; s < 11; s++) if (s <= cnt && kt[s] > m) m = kt[s];
        float Z = 0.f, P = 0.f;
        #pragma unroll
        for (int s = 0; s < 11; s++)
            if (s <= cnt) { float e = __expf(kt[s]-m); Z += e; P += e*gv[s]; }
        out[b*TT + 1 + t] = fsig(__fdividef(P, Z));
    }
}

__global__ void tail_k(const float* __restrict__ L, float* __restrict__ out) {
    int i = blockIdx.x*blockDim.x + threadIdx.x;
    if (i < BB) out[i*TT] = 0.5f;
    if (i < BB*DD) {
        int b = i / DD;
        out[BB*TT + i] = L[((size_t)b*TM + (TM-1))*DD + (i - b*DD)];
    }
}

// ---------------- launch ----------------

extern "C" void kernel_launch(void* const* d_in, const int* in_sizes, int n_in,
                              void* d_out, int out_size) {
    const int*   question = (const int*)d_in[0];
    const int*   response = (const int*)d_in[1];
    const int*   maskp    = (const int*)d_in[2];
    const int*   q_nb     = (const int*)d_in[3];
    const int*   s_nb     = (const int*)d_in[4];
    const int*   skidx    = (const int*)d_in[5];
    const int*   skmask   = (const int*)d_in[6];
    const float* emb_q    = (const float*)d_in[7];
    const float* emb_s    = (const float*)d_in[8];
    const float* emb_r    = (const float*)d_in[9];
    const float* Wih      = (const float*)d_in[10];
    const float* lb       = (const float*)d_in[11];
    const float* aggW     = (const float*)d_in[12];
    const float* aggb     = (const float*)d_in[13];
    const float* aggLW    = (const float*)d_in[14];
    const float* aggLb    = (const float*)d_in[15];
    const float* Wq       = (const float*)d_in[16];
    const float* bq       = (const float*)d_in[17];
    const float* w_att    = (const float*)d_in[20];
    float* out = (float*)d_out;

    float* buf = nullptr; float* ktb = nullptr; int* topk = nullptr;
    cudaGetSymbolAddress((void**)&buf,  g_buf);
    cudaGetSymbolAddress((void**)&ktb,  g_kt);
    cudaGetSymbolAddress((void**)&topk, g_topk);

    float* pX2  = buf + OFF_X2;
    float* pE2  = buf + OFF_E2;
    float* pX1  = buf + OFF_X1;
    float* pE1  = buf + OFF_E1;
    float* pX0  = buf + OFF_X0;
    float* pE0a = buf + OFF_E0A;
    float* pE0b = buf + OFF_E0B;
    float* pE0c = buf + OFF_E0C;
    float* pE1b = buf + OFF_E1B;
    float* pAGG = buf + OFF_AGG;
    float* pG   = buf + OFF_G;
    float* pL   = buf + OFF_L;

    const int AFF_SMEM = (10200 + 48*104 + 100 + 100)*4;
    const int GAT_SMEM = (20200 + 32*204 + 100)*4;
    const int SCO_SMEM = (199*101 + 8*104 + 8*200)*4 + 200*4;
    cudaFuncSetAttribute(affine48_k<0,false>, cudaFuncAttributeMaxDynamicSharedMemorySize, AFF_SMEM);
    cudaFuncSetAttribute(affine48_k<1,false>, cudaFuncAttributeMaxDynamicSharedMemorySize, AFF_SMEM);
    cudaFuncSetAttribute(affine48_k<2,true>,  cudaFuncAttributeMaxDynamicSharedMemorySize, AFF_SMEM);
    cudaFuncSetAttribute(gates32_k,           cudaFuncAttributeMaxDynamicSharedMemorySize, GAT_SMEM);
    cudaFuncSetAttribute(scores_topk_k,       cudaFuncAttributeMaxDynamicSharedMemorySize, SCO_SMEM);

    AP a;
    a.X = nullptr; a.base = nullptr; a.kids = nullptr;
    a.L = nullptr; a.topk = nullptr; a.w2 = nullptr;

    // ---- GNN aggregation ----
    build_x2_k<<<R2/4, 128>>>(question, q_nb, s_nb, emb_q, emb_s, pX2);
    a.X = pX2; a.W = aggW + 20000; a.bias = aggb + 200; a.Y = pE2;
    affine48_k<0,false><<<(R2+47)/48, 256, AFF_SMEM>>>(a, R2);

    build_x1_k<<<R1/4, 128>>>(question, q_nb, s_nb, emb_q, emb_s, pX1);
    a.X = pX1; a.W = aggW + 10000; a.bias = aggb + 100; a.Y = pE1;
    affine48_k<0,false><<<(R1+47)/48, 256, AFF_SMEM>>>(a, R1);

    build_x0_k<<<NN/4, 128>>>(question, q_nb, emb_q, emb_s, pX0);
    a.X = pX0; a.W = aggW; a.bias = aggb; a.Y = pE0a;
    affine48_k<0,false><<<(NN+47)/48, 256, AFF_SMEM>>>(a, NN);

    a.base = pE0a; a.kids = pE1; a.W = aggW; a.bias = aggb; a.Y = pE0b;
    affine48_k<1,false><<<(NN+47)/48, 256, AFF_SMEM>>>(a, NN);

    a.base = pE1; a.kids = pE2; a.W = aggW + 10000; a.bias = aggb + 100; a.Y = pE1b;
    affine48_k<1,false><<<(R1+47)/48, 256, AFF_SMEM>>>(a, R1);

    a.base = pE0b; a.kids = pE1b; a.W = aggW; a.bias = aggb; a.Y = pE0c;
    affine48_k<1,false><<<(NN+47)/48, 256, AFF_SMEM>>>(a, NN);

    a.X = pE0c; a.base = nullptr; a.kids = nullptr; a.W = aggLW; a.bias = aggLb; a.Y = pAGG;
    affine48_k<0,false><<<(NN+47)/48, 256, AFF_SMEM>>>(a, NN);

    // ---- LSTM ----
    gates32_k<<<dim3((NN+31)/32, 3), 256, GAT_SMEM>>>(question, response, maskp,
                                                      emb_q, emb_r, pAGG, Wih, lb, pG);
    lstm_pw_k<<<(NN*DD + 255)/256, 256>>>(pG, pL);

    // ---- scores + top-10 ----
    scores_topk_k<<<dim3(BB, 25), 256, SCO_SMEM>>>(question, emb_q, topk);

    // ---- attention: kt scalars (fused hist gather + affine + dot) ----
    a.X = nullptr; a.L = pL; a.topk = topk;
    a.W = Wq; a.bias = bq; a.w2 = w_att + 100; a.Y = ktb;
    affine48_k<2,true><<<(RH+47)/48, 256, AFF_SMEM>>>(a, RH);

    final_k<<<NN/4, 128>>>(question, skidx, skmask, emb_q, emb_s, pL, topk, ktb, out);
    tail_k<<<(BB*DD + 255)/256, 256>>>(pL, out);
}

// round 5
// speedup vs baseline: 1.6006x; 1.1622x over previous
#include <cuda_runtime.h>
#include <math.h>

#define BB 32
#define TT 200
#define TM 199
#define NN (BB*TM)        // 6368
#define DD 100
#define KK 10
#define R2 (NN*16)        // 101888
#define R1 (NN*4)         // 25472

#define NB0 2123          // ceil(R2/48)
#define NB1 531           // ceil(R1/48)
#define NB2 133           // ceil(NN/48)

typedef unsigned long long ull;

// ---------------- scratch ----------------
__device__ float g_buf[17830400];
__device__ int   g_topk[NN*KK];

static constexpr size_t OFF_E2  = 0;          // R2*100 = 10188800
static constexpr size_t OFF_E1  = 10188800;   // R1*100 = 2547200
static constexpr size_t OFF_E0A = 12736000;   // NN*100 = 636800
static constexpr size_t OFF_E1B = 13372800;   // R1*100
static constexpr size_t OFF_E0B = 15920000;   // NN*100
static constexpr size_t OFF_AGG = 16556800;   // NN*100
static constexpr size_t OFF_L   = 17193600;   // NN*100

// ---------------- helpers ----------------
__device__ __forceinline__ void fma2(ull& a, ull x, ull w){
    asm("fma.rn.f32x2 %0, %1, %2, %0;" : "+l"(a) : "l"(x), "l"(w));
}
__device__ __forceinline__ float unpack_sum(ull a){
    float lo = __int_as_float((int)(unsigned int)a);
    float hi = __int_as_float((int)(unsigned int)(a >> 32));
    return lo + hi;
}
__device__ __forceinline__ float ftanh(float x){
    float e = __expf(2.f*x);
    return 1.f - __fdividef(2.f, e + 1.f);
}
__device__ __forceinline__ float fsig(float x){
    return __fdividef(1.f, 1.f + __expf(-x));
}

// load 100x100 W into smem pitch 102 (51 ull words; conflict-free LDS.64)
__device__ __forceinline__ void loadW100(const float* __restrict__ W, float* Ws, int tid){
    for (int j = tid; j < 2500; j += 256){
        float4 v = ((const float4*)W)[j];
        int b4 = 4*j; int o = b4/100; int d = b4 - o*100;
        float2* ws = (float2*)&Ws[o*102 + d];
        ws[0] = make_float2(v.x, v.y);
        ws[1] = make_float2(v.z, v.w);
    }
}

// 6-rows-per-thread 100-d core; Xs pitch 104 (52 ull), Ws pitch 102 (51 ull)
__device__ __forceinline__ void core100(const float* Ws, const float* Xs, int wy,
                                        const int* col, ull acc[6][4]){
    const ull* WsU = (const ull*)Ws;
    const ull* XsU = (const ull*)Xs;
    int xbase = wy*6*52;
    #pragma unroll 1
    for (int d = 0; d < 100; d += 4){
        int dw = d >> 1;
        ull w01[4], w23[4];
        #pragma unroll
        for (int c = 0; c < 4; c++){
            int wb = col[c]*51 + dw;
            w01[c] = WsU[wb]; w23[c] = WsU[wb+1];
        }
        #pragma unroll
        for (int k = 0; k < 6; k++){
            int xb = xbase + k*52 + dw;
            ull x01 = XsU[xb], x23 = XsU[xb+1];
            #pragma unroll
            for (int c = 0; c < 4; c++){
                fma2(acc[k][c], x01, w01[c]);
                fma2(acc[k][c], x23, w23[c]);
            }
        }
    }
}

// ---------------- stage B: fused gather + affine, 3 segments in one grid ----------------

__global__ __launch_bounds__(256) void stageB_k(
    const int* __restrict__ question, const int* __restrict__ q_nb,
    const int* __restrict__ s_nb, const float* __restrict__ emb_q,
    const float* __restrict__ emb_s, const float* __restrict__ aggW,
    const float* __restrict__ aggb, float* __restrict__ E2,
    float* __restrict__ E1, float* __restrict__ E0){
    extern __shared__ float sm[];
    float* Ws = sm;            // 10200
    float* Xs = sm + 10200;    // 48*104
    float* bs = Xs + 48*104;   // 100
    int tid = threadIdx.x, wy = tid >> 5, lane = tid & 31;
    int bid = blockIdx.x;

    int seg, r0, R; const float* W; const float* bias; float* Y;
    if (bid < NB0)            { seg=0; r0=bid*48;            R=R2; W=aggW+20000; bias=aggb+200; Y=E2; }
    else if (bid < NB0+NB1)   { seg=1; r0=(bid-NB0)*48;      R=R1; W=aggW+10000; bias=aggb+100; Y=E1; }
    else                      { seg=2; r0=(bid-NB0-NB1)*48;  R=NN; W=aggW;       bias=aggb;     Y=E0; }

    loadW100(W, Ws, tid);
    if (tid < 100) bs[tid] = bias[tid];

    for (int rr = wy; rr < 48; rr += 8){
        if (lane < 25){
            int r = r0 + rr;
            float4 val = make_float4(0.f,0.f,0.f,0.f);
            if (r < R){
                const float* basep; const int* nb; const float* tbl;
                if (seg == 0){
                    int n = r >> 4, k = (r >> 2) & 3, s = r & 3;
                    int b = n / TM, t = n - b*TM;
                    int q  = question[b*TT + t];
                    int sk = q_nb[q*4 + k];
                    int q2 = s_nb[sk*4 + s];
                    basep = emb_q + (size_t)q2*DD; nb = q_nb + q2*4; tbl = emb_s;
                } else if (seg == 1){
                    int n = r >> 2, k = r & 3;
                    int b = n / TM, t = n - b*TM;
                    int q  = question[b*TT + t];
                    int sk = q_nb[q*4 + k];
                    basep = emb_s + (size_t)sk*DD; nb = s_nb + sk*4; tbl = emb_q;
                } else {
                    int b = r / TM, t = r - b*TM;
                    int q = question[b*TT + t];
                    basep = emb_q + (size_t)q*DD; nb = q_nb + q*4; tbl = emb_s;
                }
                int i0 = nb[0], i1 = nb[1], i2 = nb[2], i3 = nb[3];
                float4 bb = ((const float4*)basep)[lane];
                float4 a = ((const float4*)(tbl + (size_t)i0*DD))[lane];
                float4 c = ((const float4*)(tbl + (size_t)i1*DD))[lane];
                float4 d = ((const float4*)(tbl + (size_t)i2*DD))[lane];
                float4 e = ((const float4*)(tbl + (size_t)i3*DD))[lane];
                val.x = bb.x + 0.25f*(a.x+c.x+d.x+e.x);
                val.y = bb.y + 0.25f*(a.y+c.y+d.y+e.y);
                val.z = bb.z + 0.25f*(a.z+c.z+d.z+e.z);
                val.w = bb.w + 0.25f*(a.w+c.w+d.w+e.w);
            }
            *(float4*)&Xs[rr*104 + 4*lane] = val;
        }
    }
    __syncthreads();

    int c3 = (lane < 4) ? 96 + lane : 96;
    int col[4] = {lane, lane+32, lane+64, c3};
    ull acc[6][4];
    #pragma unroll
    for (int k = 0; k < 6; k++)
        #pragma unroll
        for (int c = 0; c < 4; c++) acc[k][c] = 0ull;
    core100(Ws, Xs, wy, col, acc);

    #pragma unroll
    for (int k = 0; k < 6; k++){
        int r = r0 + wy*6 + k;
        if (r >= R) continue;
        float* yo = Y + (size_t)r*100;
        yo[col[0]] = ftanh(unpack_sum(acc[k][0]) + bs[col[0]]);
        yo[col[1]] = ftanh(unpack_sum(acc[k][1]) + bs[col[1]]);
        yo[col[2]] = ftanh(unpack_sum(acc[k][2]) + bs[col[2]]);
        if (lane < 4) yo[col[3]] = ftanh(unpack_sum(acc[k][3]) + bs[col[3]]);
    }
}

// ---------------- stage C: X = base + 0.25*sum(kids), two segments ----------------

__global__ __launch_bounds__(256) void stageC_k(
    const float* __restrict__ E1, const float* __restrict__ E2,
    const float* __restrict__ E0a,
    const float* __restrict__ aggW, const float* __restrict__ aggb,
    float* __restrict__ E1b, float* __restrict__ E0b){
    extern __shared__ float sm[];
    float* Ws = sm;
    float* Xs = sm + 10200;
    float* bs = Xs + 48*104;
    int tid = threadIdx.x, wy = tid >> 5, lane = tid & 31;
    int bid = blockIdx.x;

    int r0, R; const float* basep; const float* kids; const float* W; const float* bias; float* Y;
    if (bid < NB1){ r0=bid*48; R=R1; basep=E1; kids=E2; W=aggW+10000; bias=aggb+100; Y=E1b; }
    else          { r0=(bid-NB1)*48; R=NN; basep=E0a; kids=E1; W=aggW; bias=aggb; Y=E0b; }

    loadW100(W, Ws, tid);
    if (tid < 100) bs[tid] = bias[tid];

    for (int rr = wy; rr < 48; rr += 8){
        if (lane < 25){
            int r = r0 + rr;
            float4 val = make_float4(0.f,0.f,0.f,0.f);
            if (r < R){
                const float4* bp = (const float4*)(basep + (size_t)r*100);
                const float4* kp = (const float4*)(kids + (size_t)r*400);
                float4 a = kp[lane], b = kp[25+lane], c = kp[50+lane], d4 = kp[75+lane];
                float4 bb = bp[lane];
                val.x = bb.x + 0.25f*(a.x+b.x+c.x+d4.x);
                val.y = bb.y + 0.25f*(a.y+b.y+c.y+d4.y);
                val.z = bb.z + 0.25f*(a.z+b.z+c.z+d4.z);
                val.w = bb.w + 0.25f*(a.w+b.w+c.w+d4.w);
            }
            *(float4*)&Xs[rr*104 + 4*lane] = val;
        }
    }
    __syncthreads();

    int c3 = (lane < 4) ? 96 + lane : 96;
    int col[4] = {lane, lane+32, lane+64, c3};
    ull acc[6][4];
    #pragma unroll
    for (int k = 0; k < 6; k++)
        #pragma unroll
        for (int c = 0; c < 4; c++) acc[k][c] = 0ull;
    core100(Ws, Xs, wy, col, acc);

    #pragma unroll
    for (int k = 0; k < 6; k++){
        int r = r0 + wy*6 + k;
        if (r >= R) continue;
        float* yo = Y + (size_t)r*100;
        yo[col[0]] = ftanh(unpack_sum(acc[k][0]) + bs[col[0]]);
        yo[col[1]] = ftanh(unpack_sum(acc[k][1]) + bs[col[1]]);
        yo[col[2]] = ftanh(unpack_sum(acc[k][2]) + bs[col[2]]);
        if (lane < 4) yo[col[3]] = ftanh(unpack_sum(acc[k][3]) + bs[col[3]]);
    }
}

// ---------------- stage D: chained double affine (e0 pass2 + aggL) ----------------

__global__ __launch_bounds__(256) void stageD_k(
    const float* __restrict__ E0b, const float* __restrict__ E1b,
    const float* __restrict__ aggW, const float* __restrict__ aggb,
    const float* __restrict__ aggLW, const float* __restrict__ aggLb,
    float* __restrict__ AGG){
    extern __shared__ float sm[];
    float* Ws = sm;
    float* Xs = sm + 10200;
    float* bs = Xs + 48*104;
    int tid = threadIdx.x, wy = tid >> 5, lane = tid & 31;
    int r0 = blockIdx.x * 48;

    loadW100(aggW, Ws, tid);
    if (tid < 100) bs[tid] = aggb[tid];

    for (int rr = wy; rr < 48; rr += 8){
        if (lane < 25){
            int r = r0 + rr;
            float4 val = make_float4(0.f,0.f,0.f,0.f);
            if (r < NN){
                const float4* bp = (const float4*)(E0b + (size_t)r*100);
                const float4* kp = (const float4*)(E1b + (size_t)r*400);
                float4 a = kp[lane], b = kp[25+lane], c = kp[50+lane], d4 = kp[75+lane];
                float4 bb = bp[lane];
                val.x = bb.x + 0.25f*(a.x+b.x+c.x+d4.x);
                val.y = bb.y + 0.25f*(a.y+b.y+c.y+d4.y);
                val.z = bb.z + 0.25f*(a.z+b.z+c.z+d4.z);
                val.w = bb.w + 0.25f*(a.w+b.w+c.w+d4.w);
            }
            *(float4*)&Xs[rr*104 + 4*lane] = val;
        }
    }
    __syncthreads();

    int c3 = (lane < 4) ? 96 + lane : 96;
    int col[4] = {lane, lane+32, lane+64, c3};
    ull acc[6][4];
    #pragma unroll
    for (int k = 0; k < 6; k++)
        #pragma unroll
        for (int c = 0; c < 4; c++) acc[k][c] = 0ull;
    core100(Ws, Xs, wy, col, acc);

    // write tanh result back into Xs (each warp owns its 6 rows)
    #pragma unroll
    for (int k = 0; k < 6; k++){
        int rr = wy*6 + k;
        int r = r0 + rr;
        if (r >= NN) continue;   // padding rows stay zero
        Xs[rr*104 + col[0]] = ftanh(unpack_sum(acc[k][0]) + bs[col[0]]);
        Xs[rr*104 + col[1]] = ftanh(unpack_sum(acc[k][1]) + bs[col[1]]);
        Xs[rr*104 + col[2]] = ftanh(unpack_sum(acc[k][2]) + bs[col[2]]);
        if (lane < 4) Xs[rr*104 + col[3]] = ftanh(unpack_sum(acc[k][3]) + bs[col[3]]);
    }
    __syncthreads();

    loadW100(aggLW, Ws, tid);
    if (tid < 100) bs[tid] = aggLb[tid];
    __syncthreads();

    #pragma unroll
    for (int k = 0; k < 6; k++)
        #pragma unroll
        for (int c = 0; c < 4; c++) acc[k][c] = 0ull;
    core100(Ws, Xs, wy, col, acc);

    #pragma unroll
    for (int k = 0; k < 6; k++){
        int r = r0 + wy*6 + k;
        if (r >= NN) continue;
        float* yo = AGG + (size_t)r*100;
        yo[col[0]] = ftanh(unpack_sum(acc[k][0]) + bs[col[0]]);
        yo[col[1]] = ftanh(unpack_sum(acc[k][1]) + bs[col[1]]);
        yo[col[2]] = ftanh(unpack_sum(acc[k][2]) + bs[col[2]]);
        if (lane < 4) yo[col[3]] = ftanh(unpack_sum(acc[k][3]) + bs[col[3]]);
    }
}

// ---------------- fused LSTM gates + pointwise -> L, 32 rows/block (199 blocks) ----------------

__global__ __launch_bounds__(256) void gatesL_k(
    const int* __restrict__ question, const int* __restrict__ response,
    const int* __restrict__ maskp, const float* __restrict__ emb_q,
    const float* __restrict__ emb_r, const float* __restrict__ AGG,
    const float* __restrict__ Wih, const float* __restrict__ lb,
    float* __restrict__ L){
    extern __shared__ float sm[];
    float* Ws  = sm;             // 100 x 202
    float* Xs  = sm + 20200;     // 32 x 204
    float* bs3 = Xs + 32*204;    // 300
    int tid = threadIdx.x, wy = tid >> 5, lane = tid & 31;
    int r0 = blockIdx.x * 32;

    if (tid < 100){
        bs3[tid]       = lb[tid];
        bs3[100 + tid] = lb[200 + tid];
        bs3[200 + tid] = lb[300 + tid];
    }
    for (int rr = wy; rr < 32; rr += 8){
        if (lane < 25){
            int r = r0 + rr;
            int b = r / TM, t = r - b*TM;
            int q   = question[b*TT + t];
            int m   = maskp[b*TT + t];
            int rsp = response[b*TT + t];
            const float4* s1 = (const float4*)((m == 1) ? (AGG + (size_t)r*100)
                                                        : (emb_q + (size_t)q*100));
            const float4* s2 = (const float4*)(emb_r + (size_t)rsp*100);
            *(float4*)&Xs[rr*204 + 4*lane]       = s1[lane];
            *(float4*)&Xs[rr*204 + 100 + 4*lane] = s2[lane];
        }
    }

    int c3 = (lane < 4) ? 96 + lane : 96;
    int col[4] = {lane, lane+32, lane+64, c3};
    float gval[3][4][4];

    #pragma unroll 1
    for (int g = 0; g < 3; g++){
        __syncthreads();
        int ob = (g == 0) ? 0 : (g + 1)*100;
        const float* W = Wih + (size_t)ob*200;
        for (int j = tid; j < 5000; j += 256){
            float4 v = ((const float4*)W)[j];
            int b4 = 4*j; int o = b4/200; int d = b4 - o*200;
            float2* ws = (float2*)&Ws[o*202 + d];
            ws[0] = make_float2(v.x, v.y);
            ws[1] = make_float2(v.z, v.w);
        }
        __syncthreads();

        ull acc[4][4];
        #pragma unroll
        for (int k = 0; k < 4; k++)
            #pragma unroll
            for (int c = 0; c < 4; c++) acc[k][c] = 0ull;

        const ull* WsU = (const ull*)Ws;
        const ull* XsU = (const ull*)Xs;
        int xbase = wy*4*102;
        #pragma unroll 1
        for (int d = 0; d < 200; d += 4){
            int dw = d >> 1;
            ull w01[4], w23[4];
            #pragma unroll
            for (int c = 0; c < 4; c++){
                int wb = col[c]*101 + dw;
                w01[c] = WsU[wb]; w23[c] = WsU[wb+1];
            }
            #pragma unroll
            for (int k = 0; k < 4; k++){
                int xb = xbase + k*102 + dw;
                ull x01 = XsU[xb], x23 = XsU[xb+1];
                #pragma unroll
                for (int c = 0; c < 4; c++){
                    fma2(acc[k][c], x01, w01[c]);
                    fma2(acc[k][c], x23, w23[c]);
                }
            }
        }
        #pragma unroll
        for (int k = 0; k < 4; k++)
            #pragma unroll
            for (int c = 0; c < 4; c++)
                gval[g][k][c] = unpack_sum(acc[k][c]) + bs3[g*100 + col[c]];
    }

    #pragma unroll
    for (int k = 0; k < 4; k++){
        int r = r0 + wy*4 + k;
        float* lo = L + (size_t)r*100;
        #pragma unroll
        for (int c = 0; c < 4; c++){
            if (c == 3 && lane >= 4) break;
            float gi = gval[0][k][c], gg = gval[1][k][c], go = gval[2][k][c];
            lo[col[c]] = fsig(go) * ftanh(fsig(gi) * ftanh(gg));
        }
    }
}

// ---------------- scores + per-t top-10 ----------------
__global__ void scores_topk_k(const int* __restrict__ question,
                              const float* __restrict__ emb_q,
                              int* __restrict__ topk) {
    extern __shared__ float sm[];
    float* P    = sm;              // [199][101]
    float* qrow = P + 199*101;     // [8][104]
    float* srow = qrow + 8*104;    // [8][200]
    int*   qidx = (int*)(srow + 8*200);  // [200]
    int b = blockIdx.x;
    int tid = threadIdx.x, w = tid >> 5, lane = tid & 31;
    if (tid < TT) qidx[tid] = question[b*TT + tid];
    __syncthreads();
    int tmax = min(TM - 1, (int)blockIdx.y*8 + 7);
    int rmax = tmax;
    for (int i = tid; i < rmax*DD; i += 256) {
        int s = i / DD, d = i - s*DD;
        P[s*101 + d] = emb_q[(size_t)qidx[s]*DD + d];
    }
    __syncthreads();
    int t = blockIdx.y*8 + w;
    if (t >= TM) return;
    int qv = qidx[t + 1];
    for (int d = lane; d < DD; d += 32) qrow[w*104 + d] = emb_q[(size_t)qv*DD + d];
    __syncwarp();
    for (int s = lane; s < t; s += 32) {
        float acc = 0.f;
        const float* pr = P + s*101;
        const float* qr = qrow + w*104;
        #pragma unroll 4
        for (int d = 0; d < DD; d++) acc += qr[d]*pr[d];
        srow[w*200 + s] = acc;
    }
    __syncwarp();
    int n = b*TM + t;
    int cnt = min(t, KK);
    for (int sel = 0; sel < KK; sel++) {
        if (sel < cnt) {
            float bv = -3.4e38f; unsigned bi = 0xffffffffu;
            for (int s = lane; s < t; s += 32) {
                float v = srow[w*200 + s];
                if (v > bv) { bv = v; bi = (unsigned)s; }
            }
            #pragma unroll
            for (int off = 16; off; off >>= 1) {
                float    ov = __shfl_down_sync(0xffffffffu, bv, off);
                unsigned oi = __shfl_down_sync(0xffffffffu, bi, off);
                if (ov > bv || (ov == bv && oi < bi)) { bv = ov; bi = oi; }
            }
            bi = __shfl_sync(0xffffffffu, bi, 0);
            if (lane == 0) { topk[n*KK + sel] = (int)bi; srow[w*200 + bi] = -3.4e38f; }
            __syncwarp();
        } else if (lane == 0) {
            topk[n*KK + sel] = -1;
        }
    }
}

// ---------------- fused KT affine + attention + output: 4 n's (44 hist rows) / block ----------------

__global__ __launch_bounds__(256) void ktfinal_k(
    const int* __restrict__ question, const int* __restrict__ skidx,
    const int* __restrict__ skmask, const float* __restrict__ emb_q,
    const float* __restrict__ emb_s, const float* __restrict__ L,
    const int* __restrict__ topk, const float* __restrict__ Wq,
    const float* __restrict__ bq, const float* __restrict__ w_att,
    float* __restrict__ out){
    extern __shared__ float sm[];
    float* Ws  = sm;               // 10200
    float* Xs  = sm + 10200;       // 48*104
    float* bs  = Xs + 48*104;      // 100
    float* w2s = bs + 100;         // 100
    float* qsm = w2s + 100;        // 4*104
    float* ktm = qsm + 4*104;      // 48
    float* gvm = ktm + 48;         // 48
    int tid = threadIdx.x, wy = tid >> 5, lane = tid & 31;
    int n0 = blockIdx.x * 4;

    loadW100(Wq, Ws, tid);
    if (tid < 100) { bs[tid] = bq[tid]; w2s[tid] = w_att[100 + tid]; }

    // hist rows (44 real, 4 pad)
    for (int rr = wy; rr < 48; rr += 8){
        if (lane < 25){
            float4 val = make_float4(0.f,0.f,0.f,0.f);
            if (rr < 44){
                int n = n0 + rr/11, s = rr - (rr/11)*11;
                int b = n / TM, t = n - b*TM;
                int cnt = min(t, KK);
                const float* src = nullptr;
                if (s == 0) src = L + (size_t)n*100;
                else if (s-1 < cnt){
                    int idx = topk[n*KK + s - 1];
                    if (idx > 0) src = L + ((size_t)b*TM + idx)*100;
                }
                if (src) val = ((const float4*)src)[lane];
            }
            *(float4*)&Xs[rr*104 + 4*lane] = val;
        }
    }
    // qs rows (skill-augmented query), one warp per n
    if (wy < 4){
        int n = n0 + wy;
        int b = n / TM, t = n - b*TM;
        int qv = question[b*TT + t + 1];
        if (lane < 25){
            float4 v = ((const float4*)(emb_q + (size_t)qv*100))[lane];
            #pragma unroll
            for (int i = 0; i < 4; i++){
                if (skmask[qv*4 + i] != 0){
                    float4 e = ((const float4*)(emb_s + (size_t)skidx[qv*4 + i]*100))[lane];
                    v.x += e.x; v.y += e.y; v.z += e.z; v.w += e.w;
                }
            }
            *(float4*)&qsm[wy*104 + 4*lane] = v;
        }
    }
    __syncthreads();

    int c3 = (lane < 4) ? 96 + lane : 96;
    int col[4] = {lane, lane+32, lane+64, c3};
    ull acc[6][4];
    #pragma unroll
    for (int k = 0; k < 6; k++)
        #pragma unroll
        for (int c = 0; c < 4; c++) acc[k][c] = 0ull;
    core100(Ws, Xs, wy, col, acc);

    #pragma unroll
    for (int k = 0; k < 6; k++){
        int rr = wy*6 + k;
        if (rr >= 44) continue;
        int nl = rr / 11;
        float o0 = ftanh(unpack_sum(acc[k][0]) + bs[col[0]]);
        float o1 = ftanh(unpack_sum(acc[k][1]) + bs[col[1]]);
        float o2 = ftanh(unpack_sum(acc[k][2]) + bs[col[2]]);
        float o3 = ftanh(unpack_sum(acc[k][3]) + bs[col[3]]);
        float v = o0*w2s[col[0]] + o1*w2s[col[1]] + o2*w2s[col[2]];
        float g = Xs[rr*104+col[0]]*qsm[nl*104+col[0]]
                + Xs[rr*104+col[1]]*qsm[nl*104+col[1]]
                + Xs[rr*104+col[2]]*qsm[nl*104+col[2]];
        if (lane < 4){
            v += o3*w2s[col[3]];
            g += Xs[rr*104+col[3]]*qsm[nl*104+col[3]];
        }
        #pragma unroll
        for (int off = 16; off; off >>= 1){
            v += __shfl_down_sync(0xffffffffu, v, off);
            g += __shfl_down_sync(0xffffffffu, g, off);
        }
        if (lane == 0){ ktm[rr] = v; gvm[rr] = g; }
    }
    __syncthreads();

    if (tid < 4){
        int n = n0 + tid;
        int b = n / TM, t = n - b*TM;
        int cnt = min(t, KK);
        float m = -3.4e38f;
        for (int s = 0; s <= cnt; s++){ float v = ktm[tid*11 + s]; if (v > m) m = v; }
        float Z = 0.f, P = 0.f;
        for (int s = 0; s <= cnt; s++){
            float e = __expf(ktm[tid*11 + s] - m);
            Z += e; P += e*gvm[tid*11 + s];
        }
        out[b*TT + 1 + t] = fsig(__fdividef(P, Z));
    }
}

__global__ void tail_k(const float* __restrict__ L, float* __restrict__ out) {
    int i = blockIdx.x*blockDim.x + threadIdx.x;
    if (i < BB) out[i*TT] = 0.5f;
    if (i < BB*DD) {
        int b = i / DD;
        out[BB*TT + i] = L[((size_t)b*TM + (TM-1))*DD + (i - b*DD)];
    }
}

// ---------------- launch ----------------

extern "C" void kernel_launch(void* const* d_in, const int* in_sizes, int n_in,
                              void* d_out, int out_size) {
    const int*   question = (const int*)d_in[0];
    const int*   response = (const int*)d_in[1];
    const int*   maskp    = (const int*)d_in[2];
    const int*   q_nb     = (const int*)d_in[3];
    const int*   s_nb     = (const int*)d_in[4];
    const int*   skidx    = (const int*)d_in[5];
    const int*   skmask   = (const int*)d_in[6];
    const float* emb_q    = (const float*)d_in[7];
    const float* emb_s    = (const float*)d_in[8];
    const float* emb_r    = (const float*)d_in[9];
    const float* Wih      = (const float*)d_in[10];
    const float* lb       = (const float*)d_in[11];
    const float* aggW     = (const float*)d_in[12];
    const float* aggb     = (const float*)d_in[13];
    const float* aggLW    = (const float*)d_in[14];
    const float* aggLb    = (const float*)d_in[15];
    const float* Wq       = (const float*)d_in[16];
    const float* bq       = (const float*)d_in[17];
    const float* w_att    = (const float*)d_in[20];
    float* out = (float*)d_out;

    float* buf = nullptr; int* topk = nullptr;
    cudaGetSymbolAddress((void**)&buf,  g_buf);
    cudaGetSymbolAddress((void**)&topk, g_topk);

    float* pE2  = buf + OFF_E2;
    float* pE1  = buf + OFF_E1;
    float* pE0a = buf + OFF_E0A;
    float* pE1b = buf + OFF_E1B;
    float* pE0b = buf + OFF_E0B;
    float* pAGG = buf + OFF_AGG;
    float* pL   = buf + OFF_L;

    const int AFF_SMEM = (10200 + 48*104 + 100)*4;
    const int KTF_SMEM = (10200 + 48*104 + 100 + 100 + 4*104 + 48 + 48)*4;
    const int GAT_SMEM = (20200 + 32*204 + 300)*4;
    const int SCO_SMEM = (199*101 + 8*104 + 8*200)*4 + 200*4;
    cudaFuncSetAttribute(stageB_k,      cudaFuncAttributeMaxDynamicSharedMemorySize, AFF_SMEM);
    cudaFuncSetAttribute(stageC_k,      cudaFuncAttributeMaxDynamicSharedMemorySize, AFF_SMEM);
    cudaFuncSetAttribute(stageD_k,      cudaFuncAttributeMaxDynamicSharedMemorySize, AFF_SMEM);
    cudaFuncSetAttribute(gatesL_k,      cudaFuncAttributeMaxDynamicSharedMemorySize, GAT_SMEM);
    cudaFuncSetAttribute(scores_topk_k, cudaFuncAttributeMaxDynamicSharedMemorySize, SCO_SMEM);
    cudaFuncSetAttribute(ktfinal_k,     cudaFuncAttributeMaxDynamicSharedMemorySize, KTF_SMEM);

    scores_topk_k<<<dim3(BB, 25), 256, SCO_SMEM>>>(question, emb_q, topk);

    stageB_k<<<NB0+NB1+NB2, 256, AFF_SMEM>>>(question, q_nb, s_nb, emb_q, emb_s,
                                             aggW, aggb, pE2, pE1, pE0a);
    stageC_k<<<NB1+NB2, 256, AFF_SMEM>>>(pE1, pE2, pE0a, aggW, aggb, pE1b, pE0b);
    stageD_k<<<NB2, 256, AFF_SMEM>>>(pE0b, pE1b, aggW, aggb, aggLW, aggLb, pAGG);

    gatesL_k<<<NN/32, 256, GAT_SMEM>>>(question, response, maskp, emb_q, emb_r,
                                       pAGG, Wih, lb, pL);

    ktfinal_k<<<NN/4, 256, KTF_SMEM>>>(question, skidx, skmask, emb_q, emb_s,
                                       pL, topk, Wq, bq, w_att, out);
    tail_k<<<(BB*DD + 255)/256, 256>>>(pL, out);
}